// round 10
// baseline (speedup 1.0000x reference)
#include <cuda_runtime.h>
#include <cuda_bf16.h>
#include <cuda_fp16.h>
#include <math.h>
#include <stdint.h>

// ---------------- problem constants ----------------
#define NN 4096
#define DD 256
#define HH 8
#define HD 32
#define EE 65536
#define NWORDS 128
// (1/sqrt(32)) * log2(e): folded into Q so softmax weight = exp2(S)
#define QSCALE 0.25503486f

// ---------------- scratch globals (no allocs allowed) ----------------
__device__ uint32_t g_adj[NN * NWORDS];
__device__ uint32_t g_mask[NN * NWORDS];
__device__ __nv_bfloat16 g_xb[NN * DD];
__device__ __nv_bfloat16 g_Wb[4 * DD * DD];   // Wq, Wk, Wv, Wo (bf16)
__device__ __half g_Qh[NN * DD];              // fp16, pre-scaled by QSCALE
__device__ __half g_Kh[NN * DD];
__device__ __half g_Vh[NN * DD];
__device__ __nv_bfloat16 g_attb[NN * DD];     // attention output (bf16)
__device__ float g_tmp[NN * DD];

// ---------------- PTX helpers ----------------
__device__ __forceinline__ uint32_t smem_u32(const void* p) {
    uint32_t a;
    asm("{ .reg .u64 t; cvta.to.shared.u64 t, %1; cvt.u32.u64 %0, t; }"
        : "=r"(a) : "l"(p));
    return a;
}
__device__ __forceinline__ uint32_t pack_bf16x2(float lo, float hi) {
    uint32_t r;
    asm("cvt.rn.bf16x2.f32 %0, %1, %2;" : "=r"(r) : "f"(hi), "f"(lo));
    return r;
}
__device__ __forceinline__ uint32_t pack_f16x2(float lo, float hi) {
    uint32_t r;
    asm("cvt.rn.f16x2.f32 %0, %1, %2;" : "=r"(r) : "f"(hi), "f"(lo));
    return r;
}
__device__ __forceinline__ uint32_t ex2_f16x2(uint32_t x) {
    uint32_t y;
    asm("ex2.approx.f16x2 %0, %1;" : "=r"(y) : "r"(x));
    return y;
}
__device__ __forceinline__ uint32_t hadd2(uint32_t a, uint32_t b) {
    uint32_t d;
    asm("add.rn.f16x2 %0, %1, %2;" : "=r"(d) : "r"(a), "r"(b));
    return d;
}
__device__ __forceinline__ uint32_t prmt(uint32_t a, uint32_t b, uint32_t sel) {
    uint32_t d;
    asm("prmt.b32 %0, %1, %2, %3;" : "=r"(d) : "r"(a), "r"(b), "r"(sel));
    return d;
}
__device__ __forceinline__ float2 h2_to_f2(uint32_t u) {
    __half2 h = *reinterpret_cast<__half2*>(&u);
    return __half22float2(h);
}
__device__ __forceinline__ void ldsm_x4(uint32_t* r, uint32_t addr) {
    asm volatile("ldmatrix.sync.aligned.m8n8.x4.shared.b16 {%0,%1,%2,%3}, [%4];"
        : "=r"(r[0]), "=r"(r[1]), "=r"(r[2]), "=r"(r[3]) : "r"(addr));
}
__device__ __forceinline__ void ldsm_x4_t(uint32_t* r, uint32_t addr) {
    asm volatile("ldmatrix.sync.aligned.m8n8.x4.trans.shared.b16 {%0,%1,%2,%3}, [%4];"
        : "=r"(r[0]), "=r"(r[1]), "=r"(r[2]), "=r"(r[3]) : "r"(addr));
}
__device__ __forceinline__ void mma_bf16(float* c, const uint32_t* a, const uint32_t* b) {
    asm volatile(
        "mma.sync.aligned.m16n8k16.row.col.f32.bf16.bf16.f32 "
        "{%0,%1,%2,%3}, {%4,%5,%6,%7}, {%8,%9}, {%0,%1,%2,%3};"
        : "+f"(c[0]), "+f"(c[1]), "+f"(c[2]), "+f"(c[3])
        : "r"(a[0]), "r"(a[1]), "r"(a[2]), "r"(a[3]), "r"(b[0]), "r"(b[1]));
}
// fp16 in, fp16 accumulate
__device__ __forceinline__ void mma_h(uint32_t* d, const uint32_t* a, const uint32_t* b) {
    asm volatile(
        "mma.sync.aligned.m16n8k16.row.col.f16.f16.f16.f16 "
        "{%0,%1}, {%2,%3,%4,%5}, {%6,%7}, {%0,%1};"
        : "+r"(d[0]), "+r"(d[1])
        : "r"(a[0]), "r"(a[1]), "r"(a[2]), "r"(a[3]), "r"(b[0]), "r"(b[1]));
}
__device__ __forceinline__ void cp16(uint32_t dst, const void* src) {
    asm volatile("cp.async.cg.shared.global [%0], [%1], 16;" :: "r"(dst), "l"(src));
}
#define CP_COMMIT() asm volatile("cp.async.commit_group;" ::: "memory")
#define CP_WAIT(n)  asm volatile("cp.async.wait_group %0;" :: "n"(n) : "memory")

// ================= K1: bf16 casts  ∥  adjacency init (one launch) =========
// blocks [0,1280): cast x + 4 weights (4 f32 elems/thread)
// blocks [1280,3328): zero adjacency + self loops
__global__ void __launch_bounds__(256) k1_kernel(const float* __restrict__ x,
                                                 const float* __restrict__ Wq,
                                                 const float* __restrict__ Wk,
                                                 const float* __restrict__ Wv,
                                                 const float* __restrict__ Wo) {
    int b = blockIdx.x;
    if (b < 1280) {
        int i = (b * 256 + threadIdx.x) * 4;
        const float* src;
        __nv_bfloat16* dst;
        if (i < NN * DD) {
            src = x + i; dst = g_xb + i;
        } else {
            int j = i - NN * DD;
            int w = j >> 16;
            int o = j & 65535;
            src = ((w == 0) ? Wq : (w == 1) ? Wk : (w == 2) ? Wv : Wo) + o;
            dst = g_Wb + w * (DD * DD) + o;
        }
        float4 v = *(const float4*)src;
        *(uint2*)dst = make_uint2(pack_bf16x2(v.x, v.y), pack_bf16x2(v.z, v.w));
    } else {
        int idx = (b - 1280) * 256 + threadIdx.x;   // over NN*NWORDS
        int n = idx >> 7, w = idx & 127;
        uint32_t v = 0;
        if (w == (n >> 5)) v = 1u << (n & 31);
        g_adj[idx] = v;
    }
}

// ================= 4. bf16 tensor-core GEMM core =================
// C[M=4096, N=256] = A[4096,256]@W[256,256] + bias. CTA tile 64x128, BK=32.
// MODE: 0 = f16 out (scaled), 1 = f32 out
template <int MODE>
__device__ __forceinline__ void gemm_core(const __nv_bfloat16* __restrict__ A,
                                          const __nv_bfloat16* __restrict__ W,
                                          const float* __restrict__ bias,
                                          void* __restrict__ Cv, float scale) {
    __shared__ __nv_bfloat16 sA[2][64 * 40];
    __shared__ __nv_bfloat16 sB[2][32 * 136];

    const int tid = threadIdx.x;
    const int wid = tid >> 5;
    const int lane = tid & 31;
    const int m0 = blockIdx.y * 64;
    const int n0 = blockIdx.x * 128;

    const uint32_t aA = smem_u32(sA);
    const uint32_t aB = smem_u32(sB);
    const char* Abase = (const char*)A + (size_t)m0 * (DD * 2);
    const char* Bbase = (const char*)W + (size_t)n0 * 2;

    {
#pragma unroll
        for (int j = 0; j < 2; j++) {
            int t = tid + j * 128;
            int r = t >> 2, c = t & 3;
            cp16(aA + r * 80 + c * 16, Abase + (size_t)r * 512 + c * 16);
        }
#pragma unroll
        for (int j = 0; j < 4; j++) {
            int t = tid + j * 128;
            int r = t >> 4, c = t & 15;
            cp16(aB + r * 272 + c * 16, Bbase + (size_t)r * 512 + c * 16);
        }
        CP_COMMIT();
    }

    float acc[16][4];
#pragma unroll
    for (int j = 0; j < 16; j++)
        acc[j][0] = acc[j][1] = acc[j][2] = acc[j][3] = 0.f;

    const int m = lane >> 3, rr = lane & 7;
    const uint32_t a_off = (uint32_t)((wid * 16 + (m & 1) * 8 + rr) * 80 + (m >> 1) * 16);
    const uint32_t b_lane = (uint32_t)(((lane >> 3) & 1) * 8 * 272 + (lane & 7) * 272 +
                                       (lane >> 4) * 16);

    for (int t = 0; t < 8; t++) {
        if (t < 7) {
            int nb = (t + 1) & 1;
            uint32_t dA = aA + (uint32_t)nb * 5120;
            uint32_t dB = aB + (uint32_t)nb * 8704;
            const char* As = Abase + (size_t)(t + 1) * 64;
            const char* Bs = Bbase + (size_t)(t + 1) * 32 * 512;
#pragma unroll
            for (int j = 0; j < 2; j++) {
                int u = tid + j * 128;
                int r = u >> 2, c = u & 3;
                cp16(dA + r * 80 + c * 16, As + (size_t)r * 512 + c * 16);
            }
#pragma unroll
            for (int j = 0; j < 4; j++) {
                int u = tid + j * 128;
                int r = u >> 4, c = u & 15;
                cp16(dB + r * 272 + c * 16, Bs + (size_t)r * 512 + c * 16);
            }
            CP_COMMIT();
            CP_WAIT(1);
        } else {
            CP_WAIT(0);
        }
        __syncthreads();

        const uint32_t bufA = aA + (uint32_t)(t & 1) * 5120;
        const uint32_t bufB = aB + (uint32_t)(t & 1) * 8704;

        uint32_t aq[2][4];
        ldsm_x4(aq[0], bufA + a_off);
        ldsm_x4(aq[1], bufA + a_off + 32);

#pragma unroll
        for (int ks = 0; ks < 2; ks++) {
#pragma unroll
            for (int j = 0; j < 8; j++) {
                uint32_t vb[4];
                ldsm_x4_t(vb, bufB + (uint32_t)(ks * 16 * 272 + j * 32) + b_lane);
                mma_bf16(acc[2 * j],     aq[ks], vb);
                mma_bf16(acc[2 * j + 1], aq[ks], vb + 2);
            }
        }
        __syncthreads();
    }

    const int gg = lane >> 2, tig = lane & 3;
    const int r0 = m0 + wid * 16 + gg;
#pragma unroll
    for (int j = 0; j < 16; j++) {
        int col = n0 + j * 8 + 2 * tig;
        float2 b2 = __ldg((const float2*)(bias + col));
        if (MODE == 1) {
            float* Cf = (float*)Cv;
            *(float2*)(Cf + (size_t)r0 * DD + col) =
                make_float2(acc[j][0] + b2.x, acc[j][1] + b2.y);
            *(float2*)(Cf + (size_t)(r0 + 8) * DD + col) =
                make_float2(acc[j][2] + b2.x, acc[j][3] + b2.y);
        } else {
            __half* Ch = (__half*)Cv;
            *(uint32_t*)(Ch + (size_t)r0 * DD + col) =
                pack_f16x2((acc[j][0] + b2.x) * scale, (acc[j][1] + b2.y) * scale);
            *(uint32_t*)(Ch + (size_t)(r0 + 8) * DD + col) =
                pack_f16x2((acc[j][2] + b2.x) * scale, (acc[j][3] + b2.y) * scale);
        }
    }
}

// ================= K2: QKV projections  ∥  edge scatter (one launch) ======
// grid (2, 64, 4): z=0..2 -> qkv gemm; z=3 -> edge scatter (128 blocks)
__global__ void __launch_bounds__(128) k2_kernel(const int* __restrict__ ei,
                                                 const float* __restrict__ bq,
                                                 const float* __restrict__ bk,
                                                 const float* __restrict__ bv) {
    int z = blockIdx.z;
    if (z < 3) {
        const float* bias = (z == 0) ? bq : (z == 1) ? bk : bv;
        __half* C = (z == 0) ? g_Qh : (z == 1) ? g_Kh : g_Vh;
        float scale = (z == 0) ? QSCALE : 1.f;
        gemm_core<0>(g_xb, g_Wb + (size_t)z * DD * DD, bias, C, scale);
    } else {
        int bid = blockIdx.x + blockIdx.y * 2;            // 0..127
        int e = (bid * 128 + threadIdx.x) * 4;            // 4 edges/thread
        uint4 s4 = *(const uint4*)(ei + e);
        uint4 d4 = *(const uint4*)(ei + EE + e);
        atomicOr(&g_adj[s4.x * NWORDS + (d4.x >> 5)], 1u << (d4.x & 31));
        atomicOr(&g_adj[d4.x * NWORDS + (s4.x >> 5)], 1u << (s4.x & 31));
        atomicOr(&g_adj[s4.y * NWORDS + (d4.y >> 5)], 1u << (d4.y & 31));
        atomicOr(&g_adj[d4.y * NWORDS + (s4.y >> 5)], 1u << (s4.y & 31));
        atomicOr(&g_adj[s4.z * NWORDS + (d4.z >> 5)], 1u << (d4.z & 31));
        atomicOr(&g_adj[d4.z * NWORDS + (s4.z >> 5)], 1u << (s4.z & 31));
        atomicOr(&g_adj[s4.w * NWORDS + (d4.w >> 5)], 1u << (d4.w & 31));
        atomicOr(&g_adj[d4.w * NWORDS + (s4.w >> 5)], 1u << (s4.w & 31));
    }
}

// ================= 3. reach-2 mask (split neighbor list across 2 halves) ==
__global__ void __launch_bounds__(256) mask_kernel() {
    int n = blockIdx.x;
    int tid = threadIdx.x;          // 0..255
    int w = tid & 127;              // word index
    int h = tid >> 7;               // half (list stride offset)
    int lane = tid & 31;
    __shared__ uint16_t nbr[1024];
    __shared__ int cnt;
    __shared__ uint32_t accs[128];
    if (tid == 0) cnt = 0;
    __syncthreads();

    // phase 1: ballot-scan list build (first 128 threads; 1 atomic per warp)
    if (tid < 128) {
        uint32_t bits = g_adj[n * NWORDS + tid];
        int pc = __popc(bits);
        int pref = pc;
#pragma unroll
        for (int o = 1; o < 32; o <<= 1) {
            int v = __shfl_up_sync(0xFFFFFFFFu, pref, o);
            if (lane >= o) pref += v;
        }
        int wtot = __shfl_sync(0xFFFFFFFFu, pref, 31);
        int wbase = 0;
        if (lane == 0) wbase = atomicAdd(&cnt, wtot);
        wbase = __shfl_sync(0xFFFFFFFFu, wbase, 0);
        int off = wbase + pref - pc;
        while (bits) {
            int b = __ffs(bits) - 1;
            bits &= bits - 1;
            nbr[off++] = (uint16_t)((tid << 5) + b);
        }
    }
    __syncthreads();

    // phase 2: each half ORs every other list entry (half the serial chain)
    int c = cnt;
    uint32_t acc = 0;
    int i = h;
    for (; i + 6 < c; i += 8) {
        uint32_t a0 = g_adj[(int)nbr[i + 0] * NWORDS + w];
        uint32_t a1 = g_adj[(int)nbr[i + 2] * NWORDS + w];
        uint32_t a2 = g_adj[(int)nbr[i + 4] * NWORDS + w];
        uint32_t a3 = g_adj[(int)nbr[i + 6] * NWORDS + w];
        acc |= (a0 | a1) | (a2 | a3);
    }
    for (; i < c; i += 2)
        acc |= g_adj[(int)nbr[i] * NWORDS + w];

    if (h == 0) accs[w] = acc;
    __syncthreads();
    if (h == 1) g_mask[n * NWORDS + w] = accs[w] | acc;
}

__global__ void __launch_bounds__(128) wo_gemm_kernel(const float* __restrict__ bo) {
    gemm_core<1>(g_attb, g_Wb + (size_t)3 * DD * DD, bo, g_tmp, 1.f);
}

// ================= 5. mma.sync attention (fp16, f16 accum, PRMT masks) ====
// CTA: 256 threads (8 warps), 128 queries, one head. 32 kv tiles of 128 keys.
struct AttnSmemH {
    __half Qs[128 * 32];       // 8192 B (64B rows)
    __half Ks[2][128 * 40];    // 2 x 10240 B
    __half Vs[2][128 * 40];    // 2 x 10240 B
};                             // total 49152 B

__global__ void __launch_bounds__(256, 2) attn_kernel() {
    __shared__ AttnSmemH sm;
    const int tid = threadIdx.x;
    const int wid = tid >> 5;        // 0..7
    const int lane = tid & 31;
    const int h = blockIdx.y;
    const int q0 = blockIdx.x * 128;

    const uint32_t s_q = smem_u32(sm.Qs);
    const uint32_t s_k0 = smem_u32(sm.Ks[0]);
    const uint32_t s_v0 = smem_u32(sm.Vs[0]);

    const char* ksrc = (const char*)(g_Kh + h * HD);
    const char* vsrc = (const char*)(g_Vh + h * HD);

    // ---- prologue: Q + K0/V0 via cp.async ----
    {
        const char* qsrc = (const char*)(g_Qh + (size_t)q0 * DD + h * HD);
#pragma unroll
        for (int j = 0; j < 2; j++) {
            int chunk = tid + j * 256;
            int r = chunk >> 2, c = chunk & 3;
            cp16(s_q + (uint32_t)(r * 64 + c * 16), qsrc + (size_t)r * 512 + c * 16);
        }
#pragma unroll
        for (int j = 0; j < 2; j++) {
            int chunk = tid + j * 256;
            int r = chunk >> 2, c = chunk & 3;
            uint32_t off = (uint32_t)(r * 80 + c * 16);
            size_t gs = (size_t)r * 512 + c * 16;
            cp16(s_k0 + off, ksrc + gs);
            cp16(s_v0 + off, vsrc + gs);
        }
        CP_COMMIT();
    }

    const int wq0 = wid * 16;
    const int g = lane >> 2, tig = lane & 3;
    const int row0 = q0 + wq0 + g;

    uint4 mw_lo = *(const uint4*)(g_mask + (size_t)row0 * NWORDS);
    uint4 mw_hi = *(const uint4*)(g_mask + (size_t)(row0 + 8) * NWORDS);

    CP_WAIT(0);
    __syncthreads();

    uint32_t aq[2][4];
    {
        int m = lane >> 3, rr = lane & 7;
        uint32_t base = s_q + (uint32_t)((wq0 + (m & 1) * 8 + rr) * 64 + (m >> 1) * 16);
        ldsm_x4(aq[0], base);
        ldsm_x4(aq[1], base + 32);
    }

    float o[4][4];
#pragma unroll
    for (int v = 0; v < 4; v++)
#pragma unroll
        for (int i = 0; i < 4; i++) o[v][i] = 0.f;
    float ls0 = 0.f, ls1 = 0.f;

    const uint32_t k_lane_off = (uint32_t)((lane & 7) * 80 + (lane >> 3) * 16);
    const uint32_t v_lane_off = (uint32_t)(((lane >> 3) & 1) * 8 * 80 + (lane & 7) * 80 +
                                           (lane >> 4) * 16);

    for (int t = 0; t < 32; t++) {
        int buf = t & 1;
        uint4 mw_lo_n, mw_hi_n;
        if (t < 31) {
            mw_lo_n = *(const uint4*)(g_mask + (size_t)row0 * NWORDS + (t + 1) * 4);
            mw_hi_n = *(const uint4*)(g_mask + (size_t)(row0 + 8) * NWORDS + (t + 1) * 4);
            int nb = (t + 1) & 1;
            uint32_t skb = s_k0 + (uint32_t)nb * 10240;
            uint32_t svb = s_v0 + (uint32_t)nb * 10240;
            size_t tb = (size_t)(t + 1) * 128 * 512;
#pragma unroll
            for (int j = 0; j < 2; j++) {
                int chunk = tid + j * 256;
                int r = chunk >> 2, c = chunk & 3;
                uint32_t off = (uint32_t)(r * 80 + c * 16);
                size_t gs = tb + (size_t)r * 512 + c * 16;
                cp16(skb + off, ksrc + gs);
                cp16(svb + off, vsrc + gs);
            }
            CP_COMMIT();
            CP_WAIT(1);
        } else {
            CP_WAIT(0);
        }
        __syncthreads();

        const uint32_t kb_base = s_k0 + (uint32_t)buf * 10240;
        const uint32_t vb_base = s_v0 + (uint32_t)buf * 10240;
        const uint32_t mwl[4] = {mw_lo.x, mw_lo.y, mw_lo.z, mw_lo.w};
        const uint32_t mwh[4] = {mw_hi.x, mw_hi.y, mw_hi.z, mw_hi.w};

        uint32_t ap[8][4];
        uint32_t acc01 = 0, acc23 = 0;   // per-tile f16x2 row-sum accumulators
#pragma unroll
        for (int qd = 0; qd < 4; qd++) {
            uint32_t kb[4][4];
#pragma unroll
            for (int nt = 0; nt < 4; nt++)
                ldsm_x4(kb[nt], kb_base + (uint32_t)((qd * 4 + nt) * (8 * 80)) + k_lane_off);
            // mask bits -> byte MSBs (once per quad); per n-tile: single PRMT
            uint32_t w0 = mwl[qd] >> (2 * tig);
            uint32_t w1 = mwh[qd] >> (2 * tig);
            uint32_t y1 = (w0 & 0x01010101u) << 7;
            uint32_t y2 = (w0 & 0x02020202u) << 6;
            uint32_t z1 = (w1 & 0x01010101u) << 7;
            uint32_t z2 = (w1 & 0x02020202u) << 6;
#pragma unroll
            for (int nt = 0; nt < 4; nt++) {
                uint32_t sd[2] = {0u, 0u};
                mma_h(sd, aq[0], kb[nt]);
                mma_h(sd, aq[1], kb[nt] + 2);
                uint32_t sel = 0xCC88u + (uint32_t)nt * 0x1111u;
                uint32_t p01 = ex2_f16x2(sd[0]) & prmt(y1, y2, sel);
                uint32_t p23 = ex2_f16x2(sd[1]) & prmt(z1, z2, sel);
                acc01 = hadd2(acc01, p01);
                acc23 = hadd2(acc23, p23);
                int nth = qd * 4 + nt;
                ap[nth >> 1][(nth & 1) * 2 + 0] = p01;
                ap[nth >> 1][(nth & 1) * 2 + 1] = p23;
            }
        }
        // flush per-tile row sums to fp32
        {
            float2 f0 = h2_to_f2(acc01);
            float2 f1 = h2_to_f2(acc23);
            ls0 += f0.x + f0.y;
            ls1 += f1.x + f1.y;
        }

        // ---- O_tile = P @ V (f16 accum), flushed to fp32 master ----
        uint32_t of[4][2];
#pragma unroll
        for (int v = 0; v < 4; v++) { of[v][0] = 0u; of[v][1] = 0u; }
#pragma unroll
        for (int kt = 0; kt < 8; kt++) {
            uint32_t vb[4];
            uint32_t base = vb_base + (uint32_t)kt * (16 * 80) + v_lane_off;
            ldsm_x4_t(vb, base);
            mma_h(of[0], ap[kt], vb);
            mma_h(of[1], ap[kt], vb + 2);
            ldsm_x4_t(vb, base + 32);
            mma_h(of[2], ap[kt], vb);
            mma_h(of[3], ap[kt], vb + 2);
        }
#pragma unroll
        for (int v = 0; v < 4; v++) {
            float2 lo = h2_to_f2(of[v][0]);
            float2 hi = h2_to_f2(of[v][1]);
            o[v][0] += lo.x; o[v][1] += lo.y;
            o[v][2] += hi.x; o[v][3] += hi.y;
        }

        if (t < 31) { mw_lo = mw_lo_n; mw_hi = mw_hi_n; }
        __syncthreads();
    }

    // quad-reduce row sums (cols spread over tig lanes)
    ls0 += __shfl_xor_sync(0xFFFFFFFFu, ls0, 1);
    ls0 += __shfl_xor_sync(0xFFFFFFFFu, ls0, 2);
    ls1 += __shfl_xor_sync(0xFFFFFFFFu, ls1, 1);
    ls1 += __shfl_xor_sync(0xFFFFFFFFu, ls1, 2);
    float inv0 = 1.f / ls0, inv1 = 1.f / ls1;

    __nv_bfloat16* dst0 = g_attb + (size_t)row0 * DD + h * HD + 2 * tig;
    __nv_bfloat16* dst1 = dst0 + 8 * DD;
#pragma unroll
    for (int v = 0; v < 4; v++) {
        *(uint32_t*)(dst0 + v * 8) = pack_bf16x2(o[v][0] * inv0, o[v][1] * inv0);
        *(uint32_t*)(dst1 + v * 8) = pack_bf16x2(o[v][2] * inv1, o[v][3] * inv1);
    }
}

// ================= 6. residual + LayerNorm (warp-shuffle) =================
__global__ void ln_kernel(const float* __restrict__ tmp,
                          const float* __restrict__ x,
                          const float* __restrict__ w,
                          const float* __restrict__ b,
                          float* __restrict__ out) {
    int n = blockIdx.x;
    int tid = threadIdx.x;  // 256 == DD
    int wid = tid >> 5, lane = tid & 31;
    float v = tmp[n * DD + tid] + x[n * DD + tid];
    float s1 = v, s2 = v * v;
#pragma unroll
    for (int o = 16; o > 0; o >>= 1) {
        s1 += __shfl_xor_sync(0xFFFFFFFFu, s1, o);
        s2 += __shfl_xor_sync(0xFFFFFFFFu, s2, o);
    }
    __shared__ float a1[8], a2[8];
    if (lane == 0) { a1[wid] = s1; a2[wid] = s2; }
    __syncthreads();
    float t1 = 0.f, t2 = 0.f;
#pragma unroll
    for (int i = 0; i < 8; i++) { t1 += a1[i]; t2 += a2[i]; }
    float mu = t1 * (1.f / 256.f);
    float var = t2 * (1.f / 256.f) - mu * mu;
    float inv = rsqrtf(var + 1e-5f);
    out[n * DD + tid] = (v - mu) * inv * w[tid] + b[tid];
}

// ================= launch =================
extern "C" void kernel_launch(void* const* d_in, const int* in_sizes, int n_in,
                              void* d_out, int out_size) {
    const float* x   = (const float*)d_in[0];
    const int*   ei  = (const int*)d_in[1];
    const float* Wq  = (const float*)d_in[2];
    const float* bq  = (const float*)d_in[3];
    const float* Wk  = (const float*)d_in[4];
    const float* bk  = (const float*)d_in[5];
    const float* Wv  = (const float*)d_in[6];
    const float* bv  = (const float*)d_in[7];
    const float* Wo  = (const float*)d_in[8];
    const float* bo  = (const float*)d_in[9];
    const float* lnw = (const float*)d_in[10];
    const float* lnb = (const float*)d_in[11];
    float* out = (float*)d_out;

    float* gT;
    cudaGetSymbolAddress((void**)&gT, g_tmp);

    // K1: casts ∥ adjacency init
    k1_kernel<<<3328, 256>>>(x, Wq, Wk, Wv, Wo);
    // K2: QKV projections ∥ edge scatter
    k2_kernel<<<dim3(DD / 128, NN / 64, 4), 128>>>(ei, bq, bk, bv);
    // reach-2 mask
    mask_kernel<<<NN, 256>>>();
    // tensor-core attention (fp16 data, f16 accumulators)
    attn_kernel<<<dim3(NN / 128, HH), 256>>>();
    // output projection (tensor core, fp32 out) + residual + LN
    wo_gemm_kernel<<<dim3(DD / 128, NN / 64), 128>>>(bo);
    ln_kernel<<<NN, 256>>>(gT, x, lnw, lnb, out);
}

// round 11
// speedup vs baseline: 1.0330x; 1.0330x over previous
#include <cuda_runtime.h>
#include <cuda_bf16.h>
#include <cuda_fp16.h>
#include <math.h>
#include <stdint.h>

// ---------------- problem constants ----------------
#define NN 4096
#define DD 256
#define HH 8
#define HD 32
#define EE 65536
#define NWORDS 128
// (1/sqrt(32)) * log2(e): folded into Q so softmax weight = exp2(S)
#define QSCALE 0.25503486f
#define NSPLIT 2
#define TILES_PER_SPLIT 16

// ---------------- scratch globals (no allocs allowed) ----------------
__device__ uint32_t g_adj[NN * NWORDS];
__device__ uint32_t g_mask[NN * NWORDS];
__device__ __nv_bfloat16 g_xb[NN * DD];
__device__ __nv_bfloat16 g_Wb[4 * DD * DD];   // Wq, Wk, Wv, Wo (bf16)
__device__ __half g_Qh[NN * DD];              // fp16, pre-scaled by QSCALE
__device__ __half g_Kh[NN * DD];
__device__ __half g_Vh[NN * DD];
__device__ __nv_bfloat16 g_attb[NN * DD];     // attention output (bf16)
__device__ float g_tmp[NN * DD];
__device__ float g_pO[NSPLIT * NN * DD];      // split-KV partial O (unnormalized)
__device__ float g_pl[NSPLIT * HH * NN];      // split-KV partial row sums

// ---------------- PTX helpers ----------------
__device__ __forceinline__ uint32_t smem_u32(const void* p) {
    uint32_t a;
    asm("{ .reg .u64 t; cvta.to.shared.u64 t, %1; cvt.u32.u64 %0, t; }"
        : "=r"(a) : "l"(p));
    return a;
}
__device__ __forceinline__ uint32_t pack_bf16x2(float lo, float hi) {
    uint32_t r;
    asm("cvt.rn.bf16x2.f32 %0, %1, %2;" : "=r"(r) : "f"(hi), "f"(lo));
    return r;
}
__device__ __forceinline__ uint32_t pack_f16x2(float lo, float hi) {
    uint32_t r;
    asm("cvt.rn.f16x2.f32 %0, %1, %2;" : "=r"(r) : "f"(hi), "f"(lo));
    return r;
}
__device__ __forceinline__ uint32_t ex2_f16x2(uint32_t x) {
    uint32_t y;
    asm("ex2.approx.f16x2 %0, %1;" : "=r"(y) : "r"(x));
    return y;
}
__device__ __forceinline__ uint32_t hadd2(uint32_t a, uint32_t b) {
    uint32_t d;
    asm("add.rn.f16x2 %0, %1, %2;" : "=r"(d) : "r"(a), "r"(b));
    return d;
}
__device__ __forceinline__ uint32_t prmt(uint32_t a, uint32_t b, uint32_t sel) {
    uint32_t d;
    asm("prmt.b32 %0, %1, %2, %3;" : "=r"(d) : "r"(a), "r"(b), "r"(sel));
    return d;
}
__device__ __forceinline__ float2 h2_to_f2(uint32_t u) {
    __half2 h = *reinterpret_cast<__half2*>(&u);
    return __half22float2(h);
}
__device__ __forceinline__ void ldsm_x4(uint32_t* r, uint32_t addr) {
    asm volatile("ldmatrix.sync.aligned.m8n8.x4.shared.b16 {%0,%1,%2,%3}, [%4];"
        : "=r"(r[0]), "=r"(r[1]), "=r"(r[2]), "=r"(r[3]) : "r"(addr));
}
__device__ __forceinline__ void ldsm_x4_t(uint32_t* r, uint32_t addr) {
    asm volatile("ldmatrix.sync.aligned.m8n8.x4.trans.shared.b16 {%0,%1,%2,%3}, [%4];"
        : "=r"(r[0]), "=r"(r[1]), "=r"(r[2]), "=r"(r[3]) : "r"(addr));
}
__device__ __forceinline__ void mma_bf16(float* c, const uint32_t* a, const uint32_t* b) {
    asm volatile(
        "mma.sync.aligned.m16n8k16.row.col.f32.bf16.bf16.f32 "
        "{%0,%1,%2,%3}, {%4,%5,%6,%7}, {%8,%9}, {%0,%1,%2,%3};"
        : "+f"(c[0]), "+f"(c[1]), "+f"(c[2]), "+f"(c[3])
        : "r"(a[0]), "r"(a[1]), "r"(a[2]), "r"(a[3]), "r"(b[0]), "r"(b[1]));
}
// fp16 in, fp16 accumulate
__device__ __forceinline__ void mma_h(uint32_t* d, const uint32_t* a, const uint32_t* b) {
    asm volatile(
        "mma.sync.aligned.m16n8k16.row.col.f16.f16.f16.f16 "
        "{%0,%1}, {%2,%3,%4,%5}, {%6,%7}, {%0,%1};"
        : "+r"(d[0]), "+r"(d[1])
        : "r"(a[0]), "r"(a[1]), "r"(a[2]), "r"(a[3]), "r"(b[0]), "r"(b[1]));
}
__device__ __forceinline__ void cp16(uint32_t dst, const void* src) {
    asm volatile("cp.async.cg.shared.global [%0], [%1], 16;" :: "r"(dst), "l"(src));
}
#define CP_COMMIT() asm volatile("cp.async.commit_group;" ::: "memory")
#define CP_WAIT(n)  asm volatile("cp.async.wait_group %0;" :: "n"(n) : "memory")

// ================= K1: bf16 casts  ∥  adjacency init (one launch) =========
__global__ void __launch_bounds__(256) k1_kernel(const float* __restrict__ x,
                                                 const float* __restrict__ Wq,
                                                 const float* __restrict__ Wk,
                                                 const float* __restrict__ Wv,
                                                 const float* __restrict__ Wo) {
    int b = blockIdx.x;
    if (b < 1280) {
        int i = (b * 256 + threadIdx.x) * 4;
        const float* src;
        __nv_bfloat16* dst;
        if (i < NN * DD) {
            src = x + i; dst = g_xb + i;
        } else {
            int j = i - NN * DD;
            int w = j >> 16;
            int o = j & 65535;
            src = ((w == 0) ? Wq : (w == 1) ? Wk : (w == 2) ? Wv : Wo) + o;
            dst = g_Wb + w * (DD * DD) + o;
        }
        float4 v = *(const float4*)src;
        *(uint2*)dst = make_uint2(pack_bf16x2(v.x, v.y), pack_bf16x2(v.z, v.w));
    } else {
        int idx = (b - 1280) * 256 + threadIdx.x;
        int n = idx >> 7, w = idx & 127;
        uint32_t v = 0;
        if (w == (n >> 5)) v = 1u << (n & 31);
        g_adj[idx] = v;
    }
}

// ================= bf16 tensor-core GEMM core =================
template <int MODE>
__device__ __forceinline__ void gemm_core(const __nv_bfloat16* __restrict__ A,
                                          const __nv_bfloat16* __restrict__ W,
                                          const float* __restrict__ bias,
                                          void* __restrict__ Cv, float scale) {
    __shared__ __nv_bfloat16 sA[2][64 * 40];
    __shared__ __nv_bfloat16 sB[2][32 * 136];

    const int tid = threadIdx.x;
    const int wid = tid >> 5;
    const int lane = tid & 31;
    const int m0 = blockIdx.y * 64;
    const int n0 = blockIdx.x * 128;

    const uint32_t aA = smem_u32(sA);
    const uint32_t aB = smem_u32(sB);
    const char* Abase = (const char*)A + (size_t)m0 * (DD * 2);
    const char* Bbase = (const char*)W + (size_t)n0 * 2;

    {
#pragma unroll
        for (int j = 0; j < 2; j++) {
            int t = tid + j * 128;
            int r = t >> 2, c = t & 3;
            cp16(aA + r * 80 + c * 16, Abase + (size_t)r * 512 + c * 16);
        }
#pragma unroll
        for (int j = 0; j < 4; j++) {
            int t = tid + j * 128;
            int r = t >> 4, c = t & 15;
            cp16(aB + r * 272 + c * 16, Bbase + (size_t)r * 512 + c * 16);
        }
        CP_COMMIT();
    }

    float acc[16][4];
#pragma unroll
    for (int j = 0; j < 16; j++)
        acc[j][0] = acc[j][1] = acc[j][2] = acc[j][3] = 0.f;

    const int m = lane >> 3, rr = lane & 7;
    const uint32_t a_off = (uint32_t)((wid * 16 + (m & 1) * 8 + rr) * 80 + (m >> 1) * 16);
    const uint32_t b_lane = (uint32_t)(((lane >> 3) & 1) * 8 * 272 + (lane & 7) * 272 +
                                       (lane >> 4) * 16);

    for (int t = 0; t < 8; t++) {
        if (t < 7) {
            int nb = (t + 1) & 1;
            uint32_t dA = aA + (uint32_t)nb * 5120;
            uint32_t dB = aB + (uint32_t)nb * 8704;
            const char* As = Abase + (size_t)(t + 1) * 64;
            const char* Bs = Bbase + (size_t)(t + 1) * 32 * 512;
#pragma unroll
            for (int j = 0; j < 2; j++) {
                int u = tid + j * 128;
                int r = u >> 2, c = u & 3;
                cp16(dA + r * 80 + c * 16, As + (size_t)r * 512 + c * 16);
            }
#pragma unroll
            for (int j = 0; j < 4; j++) {
                int u = tid + j * 128;
                int r = u >> 4, c = u & 15;
                cp16(dB + r * 272 + c * 16, Bs + (size_t)r * 512 + c * 16);
            }
            CP_COMMIT();
            CP_WAIT(1);
        } else {
            CP_WAIT(0);
        }
        __syncthreads();

        const uint32_t bufA = aA + (uint32_t)(t & 1) * 5120;
        const uint32_t bufB = aB + (uint32_t)(t & 1) * 8704;

        uint32_t aq[2][4];
        ldsm_x4(aq[0], bufA + a_off);
        ldsm_x4(aq[1], bufA + a_off + 32);

#pragma unroll
        for (int ks = 0; ks < 2; ks++) {
#pragma unroll
            for (int j = 0; j < 8; j++) {
                uint32_t vb[4];
                ldsm_x4_t(vb, bufB + (uint32_t)(ks * 16 * 272 + j * 32) + b_lane);
                mma_bf16(acc[2 * j],     aq[ks], vb);
                mma_bf16(acc[2 * j + 1], aq[ks], vb + 2);
            }
        }
        __syncthreads();
    }

    const int gg = lane >> 2, tig = lane & 3;
    const int r0 = m0 + wid * 16 + gg;
#pragma unroll
    for (int j = 0; j < 16; j++) {
        int col = n0 + j * 8 + 2 * tig;
        float2 b2 = __ldg((const float2*)(bias + col));
        if (MODE == 1) {
            float* Cf = (float*)Cv;
            *(float2*)(Cf + (size_t)r0 * DD + col) =
                make_float2(acc[j][0] + b2.x, acc[j][1] + b2.y);
            *(float2*)(Cf + (size_t)(r0 + 8) * DD + col) =
                make_float2(acc[j][2] + b2.x, acc[j][3] + b2.y);
        } else {
            __half* Ch = (__half*)Cv;
            *(uint32_t*)(Ch + (size_t)r0 * DD + col) =
                pack_f16x2((acc[j][0] + b2.x) * scale, (acc[j][1] + b2.y) * scale);
            *(uint32_t*)(Ch + (size_t)(r0 + 8) * DD + col) =
                pack_f16x2((acc[j][2] + b2.x) * scale, (acc[j][3] + b2.y) * scale);
        }
    }
}

// ================= K2: QKV projections  ∥  edge scatter (one launch) ======
__global__ void __launch_bounds__(128) k2_kernel(const int* __restrict__ ei,
                                                 const float* __restrict__ bq,
                                                 const float* __restrict__ bk,
                                                 const float* __restrict__ bv) {
    int z = blockIdx.z;
    if (z < 3) {
        const float* bias = (z == 0) ? bq : (z == 1) ? bk : bv;
        __half* C = (z == 0) ? g_Qh : (z == 1) ? g_Kh : g_Vh;
        float scale = (z == 0) ? QSCALE : 1.f;
        gemm_core<0>(g_xb, g_Wb + (size_t)z * DD * DD, bias, C, scale);
    } else {
        int bid = blockIdx.x + blockIdx.y * 2;            // 0..127
        int e = (bid * 128 + threadIdx.x) * 4;            // 4 edges/thread
        uint4 s4 = *(const uint4*)(ei + e);
        uint4 d4 = *(const uint4*)(ei + EE + e);
        atomicOr(&g_adj[s4.x * NWORDS + (d4.x >> 5)], 1u << (d4.x & 31));
        atomicOr(&g_adj[d4.x * NWORDS + (s4.x >> 5)], 1u << (s4.x & 31));
        atomicOr(&g_adj[s4.y * NWORDS + (d4.y >> 5)], 1u << (d4.y & 31));
        atomicOr(&g_adj[d4.y * NWORDS + (s4.y >> 5)], 1u << (s4.y & 31));
        atomicOr(&g_adj[s4.z * NWORDS + (d4.z >> 5)], 1u << (d4.z & 31));
        atomicOr(&g_adj[d4.z * NWORDS + (s4.z >> 5)], 1u << (s4.z & 31));
        atomicOr(&g_adj[s4.w * NWORDS + (d4.w >> 5)], 1u << (d4.w & 31));
        atomicOr(&g_adj[d4.w * NWORDS + (s4.w >> 5)], 1u << (s4.w & 31));
    }
}

// ================= reach-2 mask (split neighbor list across 2 halves) =====
__global__ void __launch_bounds__(256) mask_kernel() {
    int n = blockIdx.x;
    int tid = threadIdx.x;
    int w = tid & 127;
    int h = tid >> 7;
    int lane = tid & 31;
    __shared__ uint16_t nbr[1024];
    __shared__ int cnt;
    __shared__ uint32_t accs[128];
    if (tid == 0) cnt = 0;
    __syncthreads();

    if (tid < 128) {
        uint32_t bits = g_adj[n * NWORDS + tid];
        int pc = __popc(bits);
        int pref = pc;
#pragma unroll
        for (int o = 1; o < 32; o <<= 1) {
            int v = __shfl_up_sync(0xFFFFFFFFu, pref, o);
            if (lane >= o) pref += v;
        }
        int wtot = __shfl_sync(0xFFFFFFFFu, pref, 31);
        int wbase = 0;
        if (lane == 0) wbase = atomicAdd(&cnt, wtot);
        wbase = __shfl_sync(0xFFFFFFFFu, wbase, 0);
        int off = wbase + pref - pc;
        while (bits) {
            int b = __ffs(bits) - 1;
            bits &= bits - 1;
            nbr[off++] = (uint16_t)((tid << 5) + b);
        }
    }
    __syncthreads();

    int c = cnt;
    uint32_t acc = 0;
    int i = h;
    for (; i + 6 < c; i += 8) {
        uint32_t a0 = g_adj[(int)nbr[i + 0] * NWORDS + w];
        uint32_t a1 = g_adj[(int)nbr[i + 2] * NWORDS + w];
        uint32_t a2 = g_adj[(int)nbr[i + 4] * NWORDS + w];
        uint32_t a3 = g_adj[(int)nbr[i + 6] * NWORDS + w];
        acc |= (a0 | a1) | (a2 | a3);
    }
    for (; i < c; i += 2)
        acc |= g_adj[(int)nbr[i] * NWORDS + w];

    if (h == 0) accs[w] = acc;
    __syncthreads();
    if (h == 1) g_mask[n * NWORDS + w] = accs[w] | acc;
}

__global__ void __launch_bounds__(128) wo_gemm_kernel(const float* __restrict__ bo) {
    gemm_core<1>(g_attb, g_Wb + (size_t)3 * DD * DD, bo, g_tmp, 1.f);
}

// ================= attention: split-KV, quad-interleaved PV, f16 O accum ==
// grid (32, 8, 2): 128 queries x 1 head x half the KV range per CTA.
struct AttnSmemH {
    __half Qs[128 * 32];       // 8192 B (64B rows)
    __half Ks[2][128 * 40];    // 2 x 10240 B
    __half Vs[2][128 * 40];    // 2 x 10240 B
};                             // total 49152 B

__global__ void __launch_bounds__(256, 3) attn_kernel() {
    __shared__ AttnSmemH sm;
    const int tid = threadIdx.x;
    const int wid = tid >> 5;
    const int lane = tid & 31;
    const int h = blockIdx.y;
    const int q0 = blockIdx.x * 128;
    const int z = blockIdx.z;
    const int t0 = z * TILES_PER_SPLIT;
    const int t1 = t0 + TILES_PER_SPLIT;

    const uint32_t s_q = smem_u32(sm.Qs);
    const uint32_t s_k0 = smem_u32(sm.Ks[0]);
    const uint32_t s_v0 = smem_u32(sm.Vs[0]);

    const char* ksrc = (const char*)(g_Kh + h * HD);
    const char* vsrc = (const char*)(g_Vh + h * HD);

    // ---- prologue: Q + K(t0)/V(t0) via cp.async ----
    {
        const char* qsrc = (const char*)(g_Qh + (size_t)q0 * DD + h * HD);
        size_t tb = (size_t)t0 * 128 * 512;
#pragma unroll
        for (int j = 0; j < 2; j++) {
            int chunk = tid + j * 256;
            int r = chunk >> 2, c = chunk & 3;
            cp16(s_q + (uint32_t)(r * 64 + c * 16), qsrc + (size_t)r * 512 + c * 16);
        }
#pragma unroll
        for (int j = 0; j < 2; j++) {
            int chunk = tid + j * 256;
            int r = chunk >> 2, c = chunk & 3;
            uint32_t off = (uint32_t)(r * 80 + c * 16);
            size_t gs = tb + (size_t)r * 512 + c * 16;
            cp16(s_k0 + off, ksrc + gs);
            cp16(s_v0 + off, vsrc + gs);
        }
        CP_COMMIT();
    }

    const int wq0 = wid * 16;
    const int g = lane >> 2, tig = lane & 3;
    const int row0 = q0 + wq0 + g;

    uint4 mw_lo = *(const uint4*)(g_mask + (size_t)row0 * NWORDS + t0 * 4);
    uint4 mw_hi = *(const uint4*)(g_mask + (size_t)(row0 + 8) * NWORDS + t0 * 4);

    CP_WAIT(0);
    __syncthreads();

    uint32_t aq[2][4];
    {
        int m = lane >> 3, rr = lane & 7;
        uint32_t base = s_q + (uint32_t)((wq0 + (m & 1) * 8 + rr) * 64 + (m >> 1) * 16);
        ldsm_x4(aq[0], base);
        ldsm_x4(aq[1], base + 32);
    }

    // persistent f16x2 O accumulators (flushed once at the end)
    uint32_t of[4][2];
#pragma unroll
    for (int v = 0; v < 4; v++) { of[v][0] = 0u; of[v][1] = 0u; }
    float ls0 = 0.f, ls1 = 0.f;

    const uint32_t k_lane_off = (uint32_t)((lane & 7) * 80 + (lane >> 3) * 16);
    const uint32_t v_lane_off = (uint32_t)(((lane >> 3) & 1) * 8 * 80 + (lane & 7) * 80 +
                                           (lane >> 4) * 16);

    for (int t = t0; t < t1; t++) {
        int buf = t & 1;
        uint4 mw_lo_n, mw_hi_n;
        if (t < t1 - 1) {
            mw_lo_n = *(const uint4*)(g_mask + (size_t)row0 * NWORDS + (t + 1) * 4);
            mw_hi_n = *(const uint4*)(g_mask + (size_t)(row0 + 8) * NWORDS + (t + 1) * 4);
            int nb = (t + 1) & 1;
            uint32_t skb = s_k0 + (uint32_t)nb * 10240;
            uint32_t svb = s_v0 + (uint32_t)nb * 10240;
            size_t tb = (size_t)(t + 1) * 128 * 512;
#pragma unroll
            for (int j = 0; j < 2; j++) {
                int chunk = tid + j * 256;
                int r = chunk >> 2, c = chunk & 3;
                uint32_t off = (uint32_t)(r * 80 + c * 16);
                size_t gs = tb + (size_t)r * 512 + c * 16;
                cp16(skb + off, ksrc + gs);
                cp16(svb + off, vsrc + gs);
            }
            CP_COMMIT();
            CP_WAIT(1);
        } else {
            CP_WAIT(0);
        }
        __syncthreads();

        const uint32_t kb_base = s_k0 + (uint32_t)buf * 10240;
        const uint32_t vb_base = s_v0 + (uint32_t)buf * 10240;
        const uint32_t mwl[4] = {mw_lo.x, mw_lo.y, mw_lo.z, mw_lo.w};
        const uint32_t mwh[4] = {mw_hi.x, mw_hi.y, mw_hi.z, mw_hi.w};

        uint32_t acc01 = 0, acc23 = 0;   // per-tile f16x2 row-sum accumulators
#pragma unroll
        for (int qd = 0; qd < 4; qd++) {
            uint32_t kb[4][4];
#pragma unroll
            for (int nt = 0; nt < 4; nt++)
                ldsm_x4(kb[nt], kb_base + (uint32_t)((qd * 4 + nt) * (8 * 80)) + k_lane_off);
            uint32_t w0 = mwl[qd] >> (2 * tig);
            uint32_t w1 = mwh[qd] >> (2 * tig);
            uint32_t y1 = (w0 & 0x01010101u) << 7;
            uint32_t y2 = (w0 & 0x02020202u) << 6;
            uint32_t z1 = (w1 & 0x01010101u) << 7;
            uint32_t z2 = (w1 & 0x02020202u) << 6;
            uint32_t ap[2][4];
#pragma unroll
            for (int nt = 0; nt < 4; nt++) {
                uint32_t sd[2] = {0u, 0u};
                mma_h(sd, aq[0], kb[nt]);
                mma_h(sd, aq[1], kb[nt] + 2);
                uint32_t sel = 0xCC88u + (uint32_t)nt * 0x1111u;
                uint32_t p01 = ex2_f16x2(sd[0]) & prmt(y1, y2, sel);
                uint32_t p23 = ex2_f16x2(sd[1]) & prmt(z1, z2, sel);
                acc01 = hadd2(acc01, p01);
                acc23 = hadd2(acc23, p23);
                ap[nt >> 1][(nt & 1) * 2 + 0] = p01;
                ap[nt >> 1][(nt & 1) * 2 + 1] = p23;
            }
            // PV for this quad's 32 kv columns (kt = qd*2, qd*2+1)
#pragma unroll
            for (int j = 0; j < 2; j++) {
                int kt = qd * 2 + j;
                uint32_t vb[4];
                uint32_t base = vb_base + (uint32_t)kt * (16 * 80) + v_lane_off;
                ldsm_x4_t(vb, base);
                mma_h(of[0], ap[j], vb);
                mma_h(of[1], ap[j], vb + 2);
                ldsm_x4_t(vb, base + 32);
                mma_h(of[2], ap[j], vb);
                mma_h(of[3], ap[j], vb + 2);
            }
        }
        // flush per-tile row sums to fp32
        {
            float2 f0 = h2_to_f2(acc01);
            float2 f1 = h2_to_f2(acc23);
            ls0 += f0.x + f0.y;
            ls1 += f1.x + f1.y;
        }

        if (t < t1 - 1) { mw_lo = mw_lo_n; mw_hi = mw_hi_n; }
        __syncthreads();
    }

    // quad-reduce row sums
    ls0 += __shfl_xor_sync(0xFFFFFFFFu, ls0, 1);
    ls0 += __shfl_xor_sync(0xFFFFFFFFu, ls0, 2);
    ls1 += __shfl_xor_sync(0xFFFFFFFFu, ls1, 1);
    ls1 += __shfl_xor_sync(0xFFFFFFFFu, ls1, 2);

    // write partial O (fp32, unnormalized) + partial l
    float* p0 = g_pO + (size_t)z * NN * DD + (size_t)row0 * DD + h * HD + 2 * tig;
    float* p1 = p0 + 8 * DD;
#pragma unroll
    for (int v = 0; v < 4; v++) {
        *(float2*)(p0 + v * 8) = h2_to_f2(of[v][0]);
        *(float2*)(p1 + v * 8) = h2_to_f2(of[v][1]);
    }
    if (tig == 0) {
        g_pl[z * HH * NN + h * NN + row0] = ls0;
        g_pl[z * HH * NN + h * NN + row0 + 8] = ls1;
    }
}

// ================= combine split-KV partials -> bf16 attended =============
__global__ void __launch_bounds__(256) combine_kernel() {
    int i = (blockIdx.x * 256 + threadIdx.x) * 4;   // over NN*DD
    int n = i >> 8;            // DD = 256
    int c = i & 255;
    int h = c >> 5;
    float l = g_pl[h * NN + n] + g_pl[HH * NN + h * NN + n];
    float inv = 1.f / l;
    float4 a = *(const float4*)(g_pO + i);
    float4 b = *(const float4*)(g_pO + NN * DD + i);
    *(uint2*)(g_attb + i) = make_uint2(
        pack_bf16x2((a.x + b.x) * inv, (a.y + b.y) * inv),
        pack_bf16x2((a.z + b.z) * inv, (a.w + b.w) * inv));
}

// ================= residual + LayerNorm (warp-shuffle) =================
__global__ void ln_kernel(const float* __restrict__ tmp,
                          const float* __restrict__ x,
                          const float* __restrict__ w,
                          const float* __restrict__ b,
                          float* __restrict__ out) {
    int n = blockIdx.x;
    int tid = threadIdx.x;  // 256 == DD
    int wid = tid >> 5, lane = tid & 31;
    float v = tmp[n * DD + tid] + x[n * DD + tid];
    float s1 = v, s2 = v * v;
#pragma unroll
    for (int o = 16; o > 0; o >>= 1) {
        s1 += __shfl_xor_sync(0xFFFFFFFFu, s1, o);
        s2 += __shfl_xor_sync(0xFFFFFFFFu, s2, o);
    }
    __shared__ float a1[8], a2[8];
    if (lane == 0) { a1[wid] = s1; a2[wid] = s2; }
    __syncthreads();
    float t1 = 0.f, t2 = 0.f;
#pragma unroll
    for (int i = 0; i < 8; i++) { t1 += a1[i]; t2 += a2[i]; }
    float mu = t1 * (1.f / 256.f);
    float var = t2 * (1.f / 256.f) - mu * mu;
    float inv = rsqrtf(var + 1e-5f);
    out[n * DD + tid] = (v - mu) * inv * w[tid] + b[tid];
}

// ================= launch =================
extern "C" void kernel_launch(void* const* d_in, const int* in_sizes, int n_in,
                              void* d_out, int out_size) {
    const float* x   = (const float*)d_in[0];
    const int*   ei  = (const int*)d_in[1];
    const float* Wq  = (const float*)d_in[2];
    const float* bq  = (const float*)d_in[3];
    const float* Wk  = (const float*)d_in[4];
    const float* bk  = (const float*)d_in[5];
    const float* Wv  = (const float*)d_in[6];
    const float* bv  = (const float*)d_in[7];
    const float* Wo  = (const float*)d_in[8];
    const float* bo  = (const float*)d_in[9];
    const float* lnw = (const float*)d_in[10];
    const float* lnb = (const float*)d_in[11];
    float* out = (float*)d_out;

    float* gT;
    cudaGetSymbolAddress((void**)&gT, g_tmp);

    // K1: casts ∥ adjacency init
    k1_kernel<<<3328, 256>>>(x, Wq, Wk, Wv, Wo);
    // K2: QKV projections ∥ edge scatter
    k2_kernel<<<dim3(DD / 128, NN / 64, 4), 128>>>(ei, bq, bk, bv);
    // reach-2 mask
    mask_kernel<<<NN, 256>>>();
    // tensor-core attention, split-KV 2-way
    attn_kernel<<<dim3(NN / 128, HH, NSPLIT), 256>>>();
    // combine partials
    combine_kernel<<<NN * DD / 1024, 256>>>();
    // output projection (tensor core, fp32 out) + residual + LN
    wo_gemm_kernel<<<dim3(DD / 128, NN / 64), 128>>>(bo);
    ln_kernel<<<NN, 256>>>(gT, x, lnw, lnb, out);
}